// round 1
// baseline (speedup 1.0000x reference)
#include <cuda_runtime.h>
#include <cstdint>

// Problem constants
#define B_ELEMS 4194304          // 2^22 samples
#define NBLK    2048
#define NTH     256

// Per-block partial sums: [center, width, valid, dir] x NBLK
__device__ float g_partials[NBLK * 4];

__device__ __forceinline__ void accum_one(float lower, float upper,
                                          float tgt, float prev,
                                          int dt, int pv,
                                          float& s_center, float& s_width,
                                          float& s_valid, float& s_dir) {
    float center = (lower + upper) * 0.5f;
    float d = tgt - center;
    s_center = fmaf(d, d, s_center);
    s_width += (upper - lower);
    s_valid += fmaxf(lower - upper, 0.0f);
    float diff = center - prev;               // pen_up = relu(diff), pen_dn = relu(-diff)
    float sel = (pv == 0) ? diff : -diff;
    s_dir += (dt != 0) ? fmaxf(sel, 0.0f) : 0.0f;
}

__global__ void __launch_bounds__(NTH, 8)
loss_partial_kernel(const float4* __restrict__ pred,   // (B,2) -> B/2 float4 (2 samples each)
                    const float4* __restrict__ target, // B/4 float4
                    const float4* __restrict__ prev,   // B/4 float4
                    const int4*   __restrict__ dt,     // B/4 int4
                    const int4*   __restrict__ pv)     // B/4 int4
{
    float s_center = 0.f, s_width = 0.f, s_valid = 0.f, s_dir = 0.f;

    const int tid    = blockIdx.x * NTH + threadIdx.x;
    const int stride = NBLK * NTH;                 // in vec4 units
    const int nvec   = B_ELEMS / 4;                // 2^20

    for (int v = tid; v < nvec; v += stride) {
        // Front-batched loads (high MLP)
        float4 p0 = pred[2 * v];                   // samples 4v,   4v+1 (l0,u0,l1,u1)
        float4 p1 = pred[2 * v + 1];               // samples 4v+2, 4v+3
        float4 t  = target[v];
        float4 pc = prev[v];
        int4   d  = dt[v];
        int4   q  = pv[v];

        accum_one(p0.x, p0.y, t.x, pc.x, d.x, q.x, s_center, s_width, s_valid, s_dir);
        accum_one(p0.z, p0.w, t.y, pc.y, d.y, q.y, s_center, s_width, s_valid, s_dir);
        accum_one(p1.x, p1.y, t.z, pc.z, d.z, q.z, s_center, s_width, s_valid, s_dir);
        accum_one(p1.z, p1.w, t.w, pc.w, d.w, q.w, s_center, s_width, s_valid, s_dir);
    }

    // Warp reduce
    #pragma unroll
    for (int off = 16; off > 0; off >>= 1) {
        s_center += __shfl_down_sync(0xFFFFFFFFu, s_center, off);
        s_width  += __shfl_down_sync(0xFFFFFFFFu, s_width,  off);
        s_valid  += __shfl_down_sync(0xFFFFFFFFu, s_valid,  off);
        s_dir    += __shfl_down_sync(0xFFFFFFFFu, s_dir,    off);
    }

    __shared__ float sh[4][NTH / 32];
    int lane = threadIdx.x & 31;
    int warp = threadIdx.x >> 5;
    if (lane == 0) {
        sh[0][warp] = s_center;
        sh[1][warp] = s_width;
        sh[2][warp] = s_valid;
        sh[3][warp] = s_dir;
    }
    __syncthreads();

    if (warp == 0) {
        float c = (lane < NTH / 32) ? sh[0][lane] : 0.f;
        float w = (lane < NTH / 32) ? sh[1][lane] : 0.f;
        float vd = (lane < NTH / 32) ? sh[2][lane] : 0.f;
        float dr = (lane < NTH / 32) ? sh[3][lane] : 0.f;
        #pragma unroll
        for (int off = 4; off > 0; off >>= 1) {
            c  += __shfl_down_sync(0xFFFFFFFFu, c,  off);
            w  += __shfl_down_sync(0xFFFFFFFFu, w,  off);
            vd += __shfl_down_sync(0xFFFFFFFFu, vd, off);
            dr += __shfl_down_sync(0xFFFFFFFFu, dr, off);
        }
        if (lane == 0) {
            g_partials[blockIdx.x * 4 + 0] = c;
            g_partials[blockIdx.x * 4 + 1] = w;
            g_partials[blockIdx.x * 4 + 2] = vd;
            g_partials[blockIdx.x * 4 + 3] = dr;
        }
    }
}

__global__ void __launch_bounds__(NTH)
loss_final_kernel(float* __restrict__ out)
{
    // 2048 partial sets reduced by 256 threads (8 each), double precision
    double c = 0.0, w = 0.0, vd = 0.0, dr = 0.0;
    for (int i = threadIdx.x; i < NBLK; i += NTH) {
        c  += (double)g_partials[i * 4 + 0];
        w  += (double)g_partials[i * 4 + 1];
        vd += (double)g_partials[i * 4 + 2];
        dr += (double)g_partials[i * 4 + 3];
    }
    // shared-memory tree reduce in double
    __shared__ double shc[NTH], shw[NTH], shv[NTH], shd[NTH];
    shc[threadIdx.x] = c; shw[threadIdx.x] = w;
    shv[threadIdx.x] = vd; shd[threadIdx.x] = dr;
    __syncthreads();
    for (int s = NTH / 2; s > 0; s >>= 1) {
        if (threadIdx.x < s) {
            shc[threadIdx.x] += shc[threadIdx.x + s];
            shw[threadIdx.x] += shw[threadIdx.x + s];
            shv[threadIdx.x] += shv[threadIdx.x + s];
            shd[threadIdx.x] += shd[threadIdx.x + s];
        }
        __syncthreads();
    }
    if (threadIdx.x == 0) {
        const double invn = 1.0 / (double)B_ELEMS;
        double center_loss  = shc[0] * invn;
        double width_loss   = shw[0] * invn;
        double valid_pen    = shv[0] * invn;
        double dir_pen      = shd[0];
        double total = center_loss * 1.5 + 0.1 * width_loss
                     + 10.0 * valid_pen + 0.5 * dir_pen * invn;
        out[0] = (float)total;
    }
}

extern "C" void kernel_launch(void* const* d_in, const int* in_sizes, int n_in,
                              void* d_out, int out_size) {
    const float4* pred   = (const float4*)d_in[0];
    const float4* target = (const float4*)d_in[1];
    const float4* prev   = (const float4*)d_in[2];
    const int4*   dt     = (const int4*)d_in[3];
    const int4*   pv     = (const int4*)d_in[4];
    float* out = (float*)d_out;

    loss_partial_kernel<<<NBLK, NTH>>>(pred, target, prev, dt, pv);
    loss_final_kernel<<<1, NTH>>>(out);
}

// round 2
// speedup vs baseline: 1.2318x; 1.2318x over previous
#include <cuda_runtime.h>
#include <cstdint>

// Problem constants
#define B_ELEMS 4194304          // 2^22 samples
#define NBLK    1184             // 148 SMs * 8 CTAs -> exactly one wave
#define NTH     256

// Per-block partial sums: [center, width, valid, dir] x NBLK
__device__ float        g_partials[NBLK * 4];
__device__ unsigned int g_count = 0;

__device__ __forceinline__ void accum_one(float lower, float upper,
                                          float tgt, float prev,
                                          int dt, int pv,
                                          float& s_center, float& s_width,
                                          float& s_valid, float& s_dir) {
    float center = (lower + upper) * 0.5f;
    float d = tgt - center;
    s_center = fmaf(d, d, s_center);
    s_width += (upper - lower);
    s_valid += fmaxf(lower - upper, 0.0f);
    float diff = center - prev;               // pen_up = relu(diff), pen_dn = relu(-diff)
    float sel = (pv == 0) ? diff : -diff;
    s_dir += (dt != 0) ? fmaxf(sel, 0.0f) : 0.0f;
}

__global__ void __launch_bounds__(NTH, 8)
loss_fused_kernel(const float4* __restrict__ pred,   // (B,2) -> 2 float4 per vec4 of samples
                  const float4* __restrict__ target, // B/4 float4
                  const float4* __restrict__ prev,   // B/4 float4
                  const int4*   __restrict__ dt,     // B/4 int4
                  const int4*   __restrict__ pv,     // B/4 int4
                  float* __restrict__ out)
{
    float s_center = 0.f, s_width = 0.f, s_valid = 0.f, s_dir = 0.f;

    const int tid    = blockIdx.x * NTH + threadIdx.x;
    const int stride = NBLK * NTH;                 // in vec4 units
    const int nvec   = B_ELEMS / 4;                // 2^20

    for (int v = tid; v < nvec; v += stride) {
        // Front-batched loads (high MLP)
        float4 p0 = pred[2 * v];                   // samples 4v,   4v+1 (l0,u0,l1,u1)
        float4 p1 = pred[2 * v + 1];               // samples 4v+2, 4v+3
        float4 t  = target[v];
        float4 pc = prev[v];
        int4   d  = dt[v];
        int4   q  = pv[v];

        accum_one(p0.x, p0.y, t.x, pc.x, d.x, q.x, s_center, s_width, s_valid, s_dir);
        accum_one(p0.z, p0.w, t.y, pc.y, d.y, q.y, s_center, s_width, s_valid, s_dir);
        accum_one(p1.x, p1.y, t.z, pc.z, d.z, q.z, s_center, s_width, s_valid, s_dir);
        accum_one(p1.z, p1.w, t.w, pc.w, d.w, q.w, s_center, s_width, s_valid, s_dir);
    }

    // ---- intra-block reduce (float) ----
    #pragma unroll
    for (int off = 16; off > 0; off >>= 1) {
        s_center += __shfl_down_sync(0xFFFFFFFFu, s_center, off);
        s_width  += __shfl_down_sync(0xFFFFFFFFu, s_width,  off);
        s_valid  += __shfl_down_sync(0xFFFFFFFFu, s_valid,  off);
        s_dir    += __shfl_down_sync(0xFFFFFFFFu, s_dir,    off);
    }

    __shared__ float sh[4][NTH / 32];
    __shared__ bool  is_last;
    int lane = threadIdx.x & 31;
    int warp = threadIdx.x >> 5;
    if (lane == 0) {
        sh[0][warp] = s_center;
        sh[1][warp] = s_width;
        sh[2][warp] = s_valid;
        sh[3][warp] = s_dir;
    }
    __syncthreads();

    if (threadIdx.x == 0) {
        float c = 0.f, w = 0.f, vd = 0.f, dr = 0.f;
        #pragma unroll
        for (int i = 0; i < NTH / 32; i++) {
            c  += sh[0][i];
            w  += sh[1][i];
            vd += sh[2][i];
            dr += sh[3][i];
        }
        g_partials[blockIdx.x * 4 + 0] = c;
        g_partials[blockIdx.x * 4 + 1] = w;
        g_partials[blockIdx.x * 4 + 2] = vd;
        g_partials[blockIdx.x * 4 + 3] = dr;
        __threadfence();
        unsigned int prev_cnt = atomicAdd(&g_count, 1u);
        is_last = (prev_cnt == (unsigned int)(gridDim.x - 1));
    }
    __syncthreads();

    // ---- last block performs final reduction ----
    if (is_last) {
        double c = 0.0, w = 0.0, vd = 0.0, dr = 0.0;
        for (int i = threadIdx.x; i < NBLK; i += NTH) {
            c  += (double)g_partials[i * 4 + 0];
            w  += (double)g_partials[i * 4 + 1];
            vd += (double)g_partials[i * 4 + 2];
            dr += (double)g_partials[i * 4 + 3];
        }
        #pragma unroll
        for (int off = 16; off > 0; off >>= 1) {
            c  += __shfl_down_sync(0xFFFFFFFFu, c,  off);
            w  += __shfl_down_sync(0xFFFFFFFFu, w,  off);
            vd += __shfl_down_sync(0xFFFFFFFFu, vd, off);
            dr += __shfl_down_sync(0xFFFFFFFFu, dr, off);
        }
        __shared__ double dsh[4][NTH / 32];
        if (lane == 0) {
            dsh[0][warp] = c;
            dsh[1][warp] = w;
            dsh[2][warp] = vd;
            dsh[3][warp] = dr;
        }
        __syncthreads();
        if (threadIdx.x == 0) {
            double fc = 0.0, fw = 0.0, fv = 0.0, fd = 0.0;
            #pragma unroll
            for (int i = 0; i < NTH / 32; i++) {
                fc += dsh[0][i];
                fw += dsh[1][i];
                fv += dsh[2][i];
                fd += dsh[3][i];
            }
            const double invn = 1.0 / (double)B_ELEMS;
            double total = (fc * invn) * 1.5 + 0.1 * (fw * invn)
                         + 10.0 * (fv * invn) + 0.5 * fd * invn;
            out[0] = (float)total;
            g_count = 0;          // reset for next graph replay (deterministic)
        }
    }
}

extern "C" void kernel_launch(void* const* d_in, const int* in_sizes, int n_in,
                              void* d_out, int out_size) {
    const float4* pred   = (const float4*)d_in[0];
    const float4* target = (const float4*)d_in[1];
    const float4* prev   = (const float4*)d_in[2];
    const int4*   dt     = (const int4*)d_in[3];
    const int4*   pv     = (const int4*)d_in[4];
    float* out = (float*)d_out;

    loss_fused_kernel<<<NBLK, NTH>>>(pred, target, prev, dt, pv, out);
}

// round 3
// speedup vs baseline: 1.3607x; 1.1047x over previous
#include <cuda_runtime.h>
#include <cstdint>

// Problem constants
#define B_ELEMS 4194304          // 2^22 samples
#define NBLK    512              // stride = 512*256 = 2^17 divides nvec=2^20 -> exactly 8 iters/thread
#define NTH     256
#define NITER   (B_ELEMS / 4 / (NBLK * NTH))   // 8

// Per-block partial sums: [center, width, valid, dir] x NBLK
__device__ float        g_partials[NBLK * 4];
__device__ unsigned int g_count = 0;

__device__ __forceinline__ void accum_one(float lower, float upper,
                                          float tgt, float prev,
                                          int dt, int pv,
                                          float& s_center, float& s_width,
                                          float& s_valid, float& s_dir) {
    float center = (lower + upper) * 0.5f;
    float d = tgt - center;
    s_center = fmaf(d, d, s_center);
    s_width += (upper - lower);
    s_valid += fmaxf(lower - upper, 0.0f);
    float diff = center - prev;               // pen_up = relu(diff), pen_dn = relu(-diff)
    float sel = (pv == 0) ? diff : -diff;
    s_dir += (dt != 0) ? fmaxf(sel, 0.0f) : 0.0f;
}

// occ=4 -> 64 regs/thread: lets ptxas keep all 6 vector loads in flight (MLP=6)
__global__ void __launch_bounds__(NTH, 4)
loss_fused_kernel(const float4* __restrict__ pred,   // (B,2) -> 2 float4 per vec4 of samples
                  const float4* __restrict__ target, // B/4 float4
                  const float4* __restrict__ prev,   // B/4 float4
                  const int4*   __restrict__ dt,     // B/4 int4
                  const int4*   __restrict__ pv,     // B/4 int4
                  float* __restrict__ out)
{
    float s_center = 0.f, s_width = 0.f, s_valid = 0.f, s_dir = 0.f;

    const int tid    = blockIdx.x * NTH + threadIdx.x;
    const int stride = NBLK * NTH;                 // in vec4 units (2^17)

    int v = tid;
    #pragma unroll 2
    for (int it = 0; it < NITER; it++, v += stride) {
        // Front-batched loads (high MLP) — 6 x 128-bit LDG
        float4 p0 = pred[2 * v];                   // samples 4v,   4v+1 (l0,u0,l1,u1)
        float4 p1 = pred[2 * v + 1];               // samples 4v+2, 4v+3
        float4 t  = target[v];
        float4 pc = prev[v];
        int4   d  = dt[v];
        int4   q  = pv[v];

        accum_one(p0.x, p0.y, t.x, pc.x, d.x, q.x, s_center, s_width, s_valid, s_dir);
        accum_one(p0.z, p0.w, t.y, pc.y, d.y, q.y, s_center, s_width, s_valid, s_dir);
        accum_one(p1.x, p1.y, t.z, pc.z, d.z, q.z, s_center, s_width, s_valid, s_dir);
        accum_one(p1.z, p1.w, t.w, pc.w, d.w, q.w, s_center, s_width, s_valid, s_dir);
    }

    // ---- intra-block reduce (float) ----
    #pragma unroll
    for (int off = 16; off > 0; off >>= 1) {
        s_center += __shfl_down_sync(0xFFFFFFFFu, s_center, off);
        s_width  += __shfl_down_sync(0xFFFFFFFFu, s_width,  off);
        s_valid  += __shfl_down_sync(0xFFFFFFFFu, s_valid,  off);
        s_dir    += __shfl_down_sync(0xFFFFFFFFu, s_dir,    off);
    }

    __shared__ float sh[4][NTH / 32];
    __shared__ bool  is_last;
    int lane = threadIdx.x & 31;
    int warp = threadIdx.x >> 5;
    if (lane == 0) {
        sh[0][warp] = s_center;
        sh[1][warp] = s_width;
        sh[2][warp] = s_valid;
        sh[3][warp] = s_dir;
    }
    __syncthreads();

    if (threadIdx.x == 0) {
        float c = 0.f, w = 0.f, vd = 0.f, dr = 0.f;
        #pragma unroll
        for (int i = 0; i < NTH / 32; i++) {
            c  += sh[0][i];
            w  += sh[1][i];
            vd += sh[2][i];
            dr += sh[3][i];
        }
        g_partials[blockIdx.x * 4 + 0] = c;
        g_partials[blockIdx.x * 4 + 1] = w;
        g_partials[blockIdx.x * 4 + 2] = vd;
        g_partials[blockIdx.x * 4 + 3] = dr;
        __threadfence();
        unsigned int prev_cnt = atomicAdd(&g_count, 1u);
        is_last = (prev_cnt == (unsigned int)(gridDim.x - 1));
    }
    __syncthreads();

    // ---- last block performs final reduction ----
    if (is_last) {
        double c = 0.0, w = 0.0, vd = 0.0, dr = 0.0;
        for (int i = threadIdx.x; i < NBLK; i += NTH) {
            c  += (double)g_partials[i * 4 + 0];
            w  += (double)g_partials[i * 4 + 1];
            vd += (double)g_partials[i * 4 + 2];
            dr += (double)g_partials[i * 4 + 3];
        }
        #pragma unroll
        for (int off = 16; off > 0; off >>= 1) {
            c  += __shfl_down_sync(0xFFFFFFFFu, c,  off);
            w  += __shfl_down_sync(0xFFFFFFFFu, w,  off);
            vd += __shfl_down_sync(0xFFFFFFFFu, vd, off);
            dr += __shfl_down_sync(0xFFFFFFFFu, dr, off);
        }
        __shared__ double dsh[4][NTH / 32];
        if (lane == 0) {
            dsh[0][warp] = c;
            dsh[1][warp] = w;
            dsh[2][warp] = vd;
            dsh[3][warp] = dr;
        }
        __syncthreads();
        if (threadIdx.x == 0) {
            double fc = 0.0, fw = 0.0, fv = 0.0, fd = 0.0;
            #pragma unroll
            for (int i = 0; i < NTH / 32; i++) {
                fc += dsh[0][i];
                fw += dsh[1][i];
                fv += dsh[2][i];
                fd += dsh[3][i];
            }
            const double invn = 1.0 / (double)B_ELEMS;
            double total = (fc * invn) * 1.5 + 0.1 * (fw * invn)
                         + 10.0 * (fv * invn) + 0.5 * fd * invn;
            out[0] = (float)total;
            g_count = 0;          // reset for next graph replay (deterministic)
        }
    }
}

extern "C" void kernel_launch(void* const* d_in, const int* in_sizes, int n_in,
                              void* d_out, int out_size) {
    const float4* pred   = (const float4*)d_in[0];
    const float4* target = (const float4*)d_in[1];
    const float4* prev   = (const float4*)d_in[2];
    const int4*   dt     = (const int4*)d_in[3];
    const int4*   pv     = (const int4*)d_in[4];
    float* out = (float*)d_out;

    loss_fused_kernel<<<NBLK, NTH>>>(pred, target, prev, dt, pv, out);
}

// round 4
// speedup vs baseline: 1.3788x; 1.0133x over previous
#include <cuda_runtime.h>
#include <cstdint>

// Problem constants
#define B_ELEMS 4194304          // 2^22 samples
#define NBLK    592              // 148 SMs * 4 CTAs -> exactly one wave, uniform per-SM load
#define NTH     256
#define NVEC    (B_ELEMS / 4)    // 2^20 vec4 groups

// Per-block partial sums: [center, width, valid, dir] x NBLK
__device__ float        g_partials[NBLK * 4];
__device__ unsigned int g_count = 0;

__device__ __forceinline__ void accum_one(float lower, float upper,
                                          float tgt, float prev,
                                          int dt, int pv,
                                          float& s_center, float& s_width,
                                          float& s_valid, float& s_dir) {
    float center = (lower + upper) * 0.5f;
    float d = tgt - center;
    s_center = fmaf(d, d, s_center);
    s_width += (upper - lower);
    s_valid += fmaxf(lower - upper, 0.0f);
    float diff = center - prev;               // pen_up = relu(diff), pen_dn = relu(-diff)
    float sel = (pv == 0) ? diff : -diff;
    s_dir += (dt != 0) ? fmaxf(sel, 0.0f) : 0.0f;
}

__device__ __forceinline__ float4 ldcs4f(const float4* p) {
    return __ldcs(p);
}
__device__ __forceinline__ int4 ldcs4i(const int4* p) {
    return __ldcs(p);
}

// occ=4 -> 64 regs/thread: lets ptxas keep all 6 vector loads in flight (MLP=6)
__global__ void __launch_bounds__(NTH, 4)
loss_fused_kernel(const float4* __restrict__ pred,   // (B,2) -> 2 float4 per vec4 of samples
                  const float4* __restrict__ target, // B/4 float4
                  const float4* __restrict__ prev,   // B/4 float4
                  const int4*   __restrict__ dt,     // B/4 int4
                  const int4*   __restrict__ pv,     // B/4 int4
                  float* __restrict__ out)
{
    float s_center = 0.f, s_width = 0.f, s_valid = 0.f, s_dir = 0.f;

    const int tid    = blockIdx.x * NTH + threadIdx.x;
    const int stride = NBLK * NTH;                 // in vec4 units

    #pragma unroll 2
    for (int v = tid; v < NVEC; v += stride) {
        // Front-batched loads (high MLP) — 6 x 128-bit LDG, streaming (no reuse)
        float4 p0 = ldcs4f(&pred[2 * v]);          // samples 4v,   4v+1 (l0,u0,l1,u1)
        float4 p1 = ldcs4f(&pred[2 * v + 1]);      // samples 4v+2, 4v+3
        float4 t  = ldcs4f(&target[v]);
        float4 pc = ldcs4f(&prev[v]);
        int4   d  = ldcs4i(&dt[v]);
        int4   q  = ldcs4i(&pv[v]);

        accum_one(p0.x, p0.y, t.x, pc.x, d.x, q.x, s_center, s_width, s_valid, s_dir);
        accum_one(p0.z, p0.w, t.y, pc.y, d.y, q.y, s_center, s_width, s_valid, s_dir);
        accum_one(p1.x, p1.y, t.z, pc.z, d.z, q.z, s_center, s_width, s_valid, s_dir);
        accum_one(p1.z, p1.w, t.w, pc.w, d.w, q.w, s_center, s_width, s_valid, s_dir);
    }

    // ---- intra-block reduce (float) ----
    #pragma unroll
    for (int off = 16; off > 0; off >>= 1) {
        s_center += __shfl_down_sync(0xFFFFFFFFu, s_center, off);
        s_width  += __shfl_down_sync(0xFFFFFFFFu, s_width,  off);
        s_valid  += __shfl_down_sync(0xFFFFFFFFu, s_valid,  off);
        s_dir    += __shfl_down_sync(0xFFFFFFFFu, s_dir,    off);
    }

    __shared__ float sh[4][NTH / 32];
    __shared__ bool  is_last;
    int lane = threadIdx.x & 31;
    int warp = threadIdx.x >> 5;
    if (lane == 0) {
        sh[0][warp] = s_center;
        sh[1][warp] = s_width;
        sh[2][warp] = s_valid;
        sh[3][warp] = s_dir;
    }
    __syncthreads();

    if (threadIdx.x == 0) {
        float c = 0.f, w = 0.f, vd = 0.f, dr = 0.f;
        #pragma unroll
        for (int i = 0; i < NTH / 32; i++) {
            c  += sh[0][i];
            w  += sh[1][i];
            vd += sh[2][i];
            dr += sh[3][i];
        }
        g_partials[blockIdx.x * 4 + 0] = c;
        g_partials[blockIdx.x * 4 + 1] = w;
        g_partials[blockIdx.x * 4 + 2] = vd;
        g_partials[blockIdx.x * 4 + 3] = dr;
        __threadfence();
        unsigned int prev_cnt = atomicAdd(&g_count, 1u);
        is_last = (prev_cnt == (unsigned int)(gridDim.x - 1));
    }
    __syncthreads();

    // ---- last block performs final reduction ----
    if (is_last) {
        double c = 0.0, w = 0.0, vd = 0.0, dr = 0.0;
        for (int i = threadIdx.x; i < NBLK; i += NTH) {
            c  += (double)g_partials[i * 4 + 0];
            w  += (double)g_partials[i * 4 + 1];
            vd += (double)g_partials[i * 4 + 2];
            dr += (double)g_partials[i * 4 + 3];
        }
        #pragma unroll
        for (int off = 16; off > 0; off >>= 1) {
            c  += __shfl_down_sync(0xFFFFFFFFu, c,  off);
            w  += __shfl_down_sync(0xFFFFFFFFu, w,  off);
            vd += __shfl_down_sync(0xFFFFFFFFu, vd, off);
            dr += __shfl_down_sync(0xFFFFFFFFu, dr, off);
        }
        __shared__ double dsh[4][NTH / 32];
        if (lane == 0) {
            dsh[0][warp] = c;
            dsh[1][warp] = w;
            dsh[2][warp] = vd;
            dsh[3][warp] = dr;
        }
        __syncthreads();
        if (threadIdx.x == 0) {
            double fc = 0.0, fw = 0.0, fv = 0.0, fd = 0.0;
            #pragma unroll
            for (int i = 0; i < NTH / 32; i++) {
                fc += dsh[0][i];
                fw += dsh[1][i];
                fv += dsh[2][i];
                fd += dsh[3][i];
            }
            const double invn = 1.0 / (double)B_ELEMS;
            double total = (fc * invn) * 1.5 + 0.1 * (fw * invn)
                         + 10.0 * (fv * invn) + 0.5 * fd * invn;
            out[0] = (float)total;
            g_count = 0;          // reset for next graph replay (deterministic)
        }
    }
}

extern "C" void kernel_launch(void* const* d_in, const int* in_sizes, int n_in,
                              void* d_out, int out_size) {
    const float4* pred   = (const float4*)d_in[0];
    const float4* target = (const float4*)d_in[1];
    const float4* prev   = (const float4*)d_in[2];
    const int4*   dt     = (const int4*)d_in[3];
    const int4*   pv     = (const int4*)d_in[4];
    float* out = (float*)d_out;

    loss_fused_kernel<<<NBLK, NTH>>>(pred, target, prev, dt, pv, out);
}

// round 5
// speedup vs baseline: 1.4109x; 1.0233x over previous
#include <cuda_runtime.h>
#include <cstdint>

// Problem constants
#define B_ELEMS 4194304          // 2^22 samples
#define NBLK    592              // 148 SMs * 4 CTAs -> exactly one wave, uniform per-SM load
#define NTH     256
#define NVEC    (B_ELEMS / 4)    // 2^20 vec4 groups

// Per-block partial sums: [center, width, valid, dir] x NBLK
__device__ float        g_partials[NBLK * 4];
__device__ unsigned int g_count = 0;

__device__ __forceinline__ void accum_one(float lower, float upper,
                                          float tgt, float prev,
                                          int dt, int pv,
                                          float& s_center, float& s_width,
                                          float& s_valid, float& s_dir) {
    float center = (lower + upper) * 0.5f;
    float d = tgt - center;
    s_center = fmaf(d, d, s_center);
    s_width += (upper - lower);
    s_valid += fmaxf(lower - upper, 0.0f);
    float diff = center - prev;               // pen_up = relu(diff), pen_dn = relu(-diff)
    float sel = (pv == 0) ? diff : -diff;
    s_dir += (dt != 0) ? fmaxf(sel, 0.0f) : 0.0f;
}

// occ=4 -> 64 regs/thread: lets ptxas keep all 6 vector loads in flight (MLP=6)
// Default cache policy: working set (96 MB) fits in GB300's ~126 MB L2, so
// repeated graph replays serve from L2 at the LTS cap (~2x HBM BW).
__global__ void __launch_bounds__(NTH, 4)
loss_fused_kernel(const float4* __restrict__ pred,   // (B,2) -> 2 float4 per vec4 of samples
                  const float4* __restrict__ target, // B/4 float4
                  const float4* __restrict__ prev,   // B/4 float4
                  const int4*   __restrict__ dt,     // B/4 int4
                  const int4*   __restrict__ pv,     // B/4 int4
                  float* __restrict__ out)
{
    float s_center = 0.f, s_width = 0.f, s_valid = 0.f, s_dir = 0.f;

    const int tid    = blockIdx.x * NTH + threadIdx.x;
    const int stride = NBLK * NTH;                 // in vec4 units

    #pragma unroll 2
    for (int v = tid; v < NVEC; v += stride) {
        // Front-batched loads (high MLP) — 6 x 128-bit LDG
        float4 p0 = pred[2 * v];                   // samples 4v,   4v+1 (l0,u0,l1,u1)
        float4 p1 = pred[2 * v + 1];               // samples 4v+2, 4v+3
        float4 t  = target[v];
        float4 pc = prev[v];
        int4   d  = dt[v];
        int4   q  = pv[v];

        accum_one(p0.x, p0.y, t.x, pc.x, d.x, q.x, s_center, s_width, s_valid, s_dir);
        accum_one(p0.z, p0.w, t.y, pc.y, d.y, q.y, s_center, s_width, s_valid, s_dir);
        accum_one(p1.x, p1.y, t.z, pc.z, d.z, q.z, s_center, s_width, s_valid, s_dir);
        accum_one(p1.z, p1.w, t.w, pc.w, d.w, q.w, s_center, s_width, s_valid, s_dir);
    }

    // ---- intra-block reduce (float) ----
    #pragma unroll
    for (int off = 16; off > 0; off >>= 1) {
        s_center += __shfl_down_sync(0xFFFFFFFFu, s_center, off);
        s_width  += __shfl_down_sync(0xFFFFFFFFu, s_width,  off);
        s_valid  += __shfl_down_sync(0xFFFFFFFFu, s_valid,  off);
        s_dir    += __shfl_down_sync(0xFFFFFFFFu, s_dir,    off);
    }

    __shared__ float sh[4][NTH / 32];
    __shared__ bool  is_last;
    int lane = threadIdx.x & 31;
    int warp = threadIdx.x >> 5;
    if (lane == 0) {
        sh[0][warp] = s_center;
        sh[1][warp] = s_width;
        sh[2][warp] = s_valid;
        sh[3][warp] = s_dir;
    }
    __syncthreads();

    if (threadIdx.x == 0) {
        float c = 0.f, w = 0.f, vd = 0.f, dr = 0.f;
        #pragma unroll
        for (int i = 0; i < NTH / 32; i++) {
            c  += sh[0][i];
            w  += sh[1][i];
            vd += sh[2][i];
            dr += sh[3][i];
        }
        g_partials[blockIdx.x * 4 + 0] = c;
        g_partials[blockIdx.x * 4 + 1] = w;
        g_partials[blockIdx.x * 4 + 2] = vd;
        g_partials[blockIdx.x * 4 + 3] = dr;
        __threadfence();
        unsigned int prev_cnt = atomicAdd(&g_count, 1u);
        is_last = (prev_cnt == (unsigned int)(gridDim.x - 1));
    }
    __syncthreads();

    // ---- last block performs final reduction ----
    if (is_last) {
        double c = 0.0, w = 0.0, vd = 0.0, dr = 0.0;
        for (int i = threadIdx.x; i < NBLK; i += NTH) {
            c  += (double)g_partials[i * 4 + 0];
            w  += (double)g_partials[i * 4 + 1];
            vd += (double)g_partials[i * 4 + 2];
            dr += (double)g_partials[i * 4 + 3];
        }
        #pragma unroll
        for (int off = 16; off > 0; off >>= 1) {
            c  += __shfl_down_sync(0xFFFFFFFFu, c,  off);
            w  += __shfl_down_sync(0xFFFFFFFFu, w,  off);
            vd += __shfl_down_sync(0xFFFFFFFFu, vd, off);
            dr += __shfl_down_sync(0xFFFFFFFFu, dr, off);
        }
        __shared__ double dsh[4][NTH / 32];
        if (lane == 0) {
            dsh[0][warp] = c;
            dsh[1][warp] = w;
            dsh[2][warp] = vd;
            dsh[3][warp] = dr;
        }
        __syncthreads();
        if (threadIdx.x == 0) {
            double fc = 0.0, fw = 0.0, fv = 0.0, fd = 0.0;
            #pragma unroll
            for (int i = 0; i < NTH / 32; i++) {
                fc += dsh[0][i];
                fw += dsh[1][i];
                fv += dsh[2][i];
                fd += dsh[3][i];
            }
            const double invn = 1.0 / (double)B_ELEMS;
            double total = (fc * invn) * 1.5 + 0.1 * (fw * invn)
                         + 10.0 * (fv * invn) + 0.5 * fd * invn;
            out[0] = (float)total;
            g_count = 0;          // reset for next graph replay (deterministic)
        }
    }
}

extern "C" void kernel_launch(void* const* d_in, const int* in_sizes, int n_in,
                              void* d_out, int out_size) {
    const float4* pred   = (const float4*)d_in[0];
    const float4* target = (const float4*)d_in[1];
    const float4* prev   = (const float4*)d_in[2];
    const int4*   dt     = (const int4*)d_in[3];
    const int4*   pv     = (const int4*)d_in[4];
    float* out = (float*)d_out;

    loss_fused_kernel<<<NBLK, NTH>>>(pred, target, prev, dt, pv, out);
}

// round 6
// speedup vs baseline: 1.5724x; 1.1145x over previous
#include <cuda_runtime.h>
#include <cstdint>

// Problem constants
#define B_ELEMS 4194304          // 2^22 samples
#define NBLK    592              // 148 SMs * 4 CTAs -> one wave, uniform per-SM load
#define NTH     256
#define NVEC    (B_ELEMS / 4)    // 2^20 vec4 groups

// Fixed-point (Q32) global accumulators: [center, width, valid, dir]
// Integer addition is exactly associative/commutative -> deterministic across
// replays regardless of block arrival order.
__device__ unsigned long long g_acc[4] = {0ull, 0ull, 0ull, 0ull};
__device__ unsigned int       g_count  = 0;

#define FP_SCALE 4294967296.0    // 2^32

__device__ __forceinline__ void accum_one(float lower, float upper,
                                          float tgt, float prev,
                                          int dt, int pv,
                                          float& s_center, float& s_width,
                                          float& s_valid, float& s_dir) {
    float center = (lower + upper) * 0.5f;
    float d = tgt - center;
    s_center = fmaf(d, d, s_center);
    s_width += (upper - lower);
    s_valid += fmaxf(lower - upper, 0.0f);
    float diff = center - prev;               // pen_up = relu(diff), pen_dn = relu(-diff)
    float sel = (pv == 0) ? diff : -diff;
    s_dir += (dt != 0) ? fmaxf(sel, 0.0f) : 0.0f;
}

// occ=4 -> 64 regs/thread: all 6 vector loads stay in flight (MLP=6)
__global__ void __launch_bounds__(NTH, 4)
loss_fused_kernel(const float4* __restrict__ pred,   // (B,2) -> 2 float4 per vec4 of samples
                  const float4* __restrict__ target, // B/4 float4
                  const float4* __restrict__ prev,   // B/4 float4
                  const int4*   __restrict__ dt,     // B/4 int4
                  const int4*   __restrict__ pv,     // B/4 int4
                  float* __restrict__ out)
{
    float s_center = 0.f, s_width = 0.f, s_valid = 0.f, s_dir = 0.f;

    const int tid    = blockIdx.x * NTH + threadIdx.x;
    const int stride = NBLK * NTH;                 // in vec4 units

    #pragma unroll 2
    for (int v = tid; v < NVEC; v += stride) {
        // Front-batched loads (high MLP) — 6 x 128-bit LDG
        float4 p0 = pred[2 * v];                   // samples 4v,   4v+1 (l0,u0,l1,u1)
        float4 p1 = pred[2 * v + 1];               // samples 4v+2, 4v+3
        float4 t  = target[v];
        float4 pc = prev[v];
        int4   d  = dt[v];
        int4   q  = pv[v];

        accum_one(p0.x, p0.y, t.x, pc.x, d.x, q.x, s_center, s_width, s_valid, s_dir);
        accum_one(p0.z, p0.w, t.y, pc.y, d.y, q.y, s_center, s_width, s_valid, s_dir);
        accum_one(p1.x, p1.y, t.z, pc.z, d.z, q.z, s_center, s_width, s_valid, s_dir);
        accum_one(p1.z, p1.w, t.w, pc.w, d.w, q.w, s_center, s_width, s_valid, s_dir);
    }

    // ---- intra-block reduce (float) ----
    #pragma unroll
    for (int off = 16; off > 0; off >>= 1) {
        s_center += __shfl_down_sync(0xFFFFFFFFu, s_center, off);
        s_width  += __shfl_down_sync(0xFFFFFFFFu, s_width,  off);
        s_valid  += __shfl_down_sync(0xFFFFFFFFu, s_valid,  off);
        s_dir    += __shfl_down_sync(0xFFFFFFFFu, s_dir,    off);
    }

    __shared__ float sh[4][NTH / 32];
    int lane = threadIdx.x & 31;
    int warp = threadIdx.x >> 5;
    if (lane == 0) {
        sh[0][warp] = s_center;
        sh[1][warp] = s_width;
        sh[2][warp] = s_valid;
        sh[3][warp] = s_dir;
    }
    __syncthreads();

    if (threadIdx.x == 0) {
        float c = 0.f, w = 0.f, vd = 0.f, dr = 0.f;
        #pragma unroll
        for (int i = 0; i < NTH / 32; i++) {
            c  += sh[0][i];
            w  += sh[1][i];
            vd += sh[2][i];
            dr += sh[3][i];
        }
        // Deterministic fixed-point accumulation (Q32, wraps handle sign)
        long long ic = __double2ll_rn((double)c  * FP_SCALE);
        long long iw = __double2ll_rn((double)w  * FP_SCALE);
        long long iv = __double2ll_rn((double)vd * FP_SCALE);
        long long id = __double2ll_rn((double)dr * FP_SCALE);
        atomicAdd(&g_acc[0], (unsigned long long)ic);
        atomicAdd(&g_acc[1], (unsigned long long)iw);
        atomicAdd(&g_acc[2], (unsigned long long)iv);
        atomicAdd(&g_acc[3], (unsigned long long)id);
        __threadfence();
        unsigned int prev_cnt = atomicAdd(&g_count, 1u);
        if (prev_cnt == (unsigned int)(NBLK - 1)) {
            // Last block: read 4 words, finish, reset state for next replay
            __threadfence();
            double fc = (double)(long long)g_acc[0] / FP_SCALE;
            double fw = (double)(long long)g_acc[1] / FP_SCALE;
            double fv = (double)(long long)g_acc[2] / FP_SCALE;
            double fd = (double)(long long)g_acc[3] / FP_SCALE;
            const double invn = 1.0 / (double)B_ELEMS;
            double total = (fc * invn) * 1.5 + 0.1 * (fw * invn)
                         + 10.0 * (fv * invn) + 0.5 * fd * invn;
            out[0] = (float)total;
            g_acc[0] = 0ull;
            g_acc[1] = 0ull;
            g_acc[2] = 0ull;
            g_acc[3] = 0ull;
            g_count  = 0;
        }
    }
}

extern "C" void kernel_launch(void* const* d_in, const int* in_sizes, int n_in,
                              void* d_out, int out_size) {
    const float4* pred   = (const float4*)d_in[0];
    const float4* target = (const float4*)d_in[1];
    const float4* prev   = (const float4*)d_in[2];
    const int4*   dt     = (const int4*)d_in[3];
    const int4*   pv     = (const int4*)d_in[4];
    float* out = (float*)d_out;

    loss_fused_kernel<<<NBLK, NTH>>>(pred, target, prev, dt, pv, out);
}